// round 6
// baseline (speedup 1.0000x reference)
#include <cuda_runtime.h>
#include <math.h>
#include <stdint.h>

#define DT 512
#define DB 256
#define DI 256
#define DH 256
#define DG 768
#define DP (DT * DB)

typedef unsigned long long u64;

// ---------------- device scratch ----------
__device__ int   g_src[DP];
__device__ int   g_order[DP];
__device__ int   g_len[DB];
__device__ int   g_maxlen;
__device__ int   g_ntrue;
__device__ float g_gi[(size_t)DP * DG];

// ---------------- f32x2 helpers ----------
__device__ __forceinline__ u64 pack2(float lo, float hi) {
    u64 r; asm("mov.b64 %0, {%1, %2};" : "=l"(r) : "f"(lo), "f"(hi)); return r;
}
__device__ __forceinline__ void unpack2(u64 v, float& lo, float& hi) {
    asm("mov.b64 {%0, %1}, %2;" : "=f"(lo), "=f"(hi) : "l"(v));
}
__device__ __forceinline__ void fma2(u64& d, u64 a, u64 b) {
    asm("fma.rn.f32x2 %0, %1, %2, %0;" : "+l"(d) : "l"(a), "l"(b));
}
__device__ __forceinline__ u64 add2(u64 a, u64 b) {
    u64 r; asm("add.rn.f32x2 %0, %1, %2;" : "=l"(r) : "l"(a), "l"(b)); return r;
}
__device__ __forceinline__ float tanh_ap(float x) {
    float r; asm("tanh.approx.f32 %0, %1;" : "=f"(r) : "f"(x)); return r;
}

// ---------------------------------------------------------------------------
// Kernel 1: lengths, packed mask, ranks, order[], src[]  (1 CTA, 1024 thr)
// ---------------------------------------------------------------------------
__global__ void k_prep(const int* __restrict__ mask) {
    __shared__ int sLen[DB];
    __shared__ int sWm[32], sWp[32];
    __shared__ int sMax;
    const int tid = threadIdx.x;
    if (tid < DB) sLen[tid] = 0;
    if (tid == 0) sMax = 0;
    __syncthreads();
    {
        const int b = tid & 255;
        int acc = 0;
        for (int t = tid >> 8; t < DT; t += 4) acc += (mask[(t << 8) + b] != 0) ? 1 : 0;
        atomicAdd(&sLen[b], acc);
    }
    __syncthreads();
    if (tid < DB) { g_len[tid] = sLen[tid]; atomicMax(&sMax, sLen[tid]); }
    __syncthreads();
    if (tid == 0) g_maxlen = sMax;

    const int base = tid << 7;
    int cm = 0, cp = 0;
    #pragma unroll 4
    for (int i = 0; i < 128; i++) {
        const int p = base + i;
        cm += (mask[p] != 0) ? 1 : 0;
        cp += ((p >> 8) < sLen[p & 255]) ? 1 : 0;
    }
    const int lane = tid & 31, wid = tid >> 5;
    int im = cm, ip = cp;
    #pragma unroll
    for (int d = 1; d < 32; d <<= 1) {
        const int um = __shfl_up_sync(0xffffffffu, im, d);
        const int up = __shfl_up_sync(0xffffffffu, ip, d);
        if (lane >= d) { im += um; ip += up; }
    }
    if (lane == 31) { sWm[wid] = im; sWp[wid] = ip; }
    __syncthreads();
    if (wid == 0) {
        const int am = sWm[lane], ap = sWp[lane];
        int jm = am, jp = ap;
        #pragma unroll
        for (int d = 1; d < 32; d <<= 1) {
            const int um = __shfl_up_sync(0xffffffffu, jm, d);
            const int up = __shfl_up_sync(0xffffffffu, jp, d);
            if (lane >= d) { jm += um; jp += up; }
        }
        sWm[lane] = jm - am;
        sWp[lane] = jp - ap;
        if (lane == 31) g_ntrue = jm;
    }
    __syncthreads();

    int mrank = sWm[wid] + im - cm;
    int prank = sWp[wid] + ip - cp;
    for (int i = 0; i < 128; i++) {
        const int p  = base + i;
        const int mt = (mask[p] != 0) ? 1 : 0;
        const int pt = ((p >> 8) < sLen[p & 255]) ? 1 : 0;
        if (mt) g_order[mrank] = p;
        g_src[p] = pt ? prank : -1;
        mrank += mt; prank += pt;
    }
    __syncthreads();
    for (int i = 0; i < 128; i++) {
        const int p = base + i;
        const int k = g_src[p];
        if (k >= 0) g_src[p] = g_order[k];
    }
}

// ---------------------------------------------------------------------------
// Kernel 2: gi = gather(x) @ W_ih^T + b_ih  (64x64x16 tile, f32x2)
// ---------------------------------------------------------------------------
__global__ void k_gi(const float* __restrict__ x,
                     const float* __restrict__ Wih,
                     const float* __restrict__ bih) {
    __shared__ float As[16][64];
    __shared__ float Bs[16][64];
    __shared__ int   sSrc[64];
    __shared__ int   sAny;
    const int tid = threadIdx.x;
    const int gt = blockIdx.x;
    const int pt = blockIdx.y;

    if (tid == 0) sAny = 0;
    __syncthreads();
    if (tid < 64) {
        const int s = g_src[(pt << 6) + tid];
        sSrc[tid] = (s >= 0) ? s : 0;
        if (s >= 0) sAny = 1;
    }
    __syncthreads();
    if (!sAny) return;

    u64 acc[4][2] = {{0ull, 0ull}, {0ull, 0ull}, {0ull, 0ull}, {0ull, 0ull}};
    const int tm = tid & 15, tn = tid >> 4;
    const int m  = tid >> 2;
    const int kk = (tid & 3) << 2;
    const float* xrow = x   + ((size_t)sSrc[m] << 8);
    const float* wrow = Wih + ((size_t)((gt << 6) + m) << 8);

    for (int k0 = 0; k0 < DI; k0 += 16) {
        const float4 av = *(const float4*)(xrow + k0 + kk);
        const float4 bv = *(const float4*)(wrow + k0 + kk);
        As[kk + 0][m] = av.x; As[kk + 1][m] = av.y; As[kk + 2][m] = av.z; As[kk + 3][m] = av.w;
        Bs[kk + 0][m] = bv.x; Bs[kk + 1][m] = bv.y; Bs[kk + 2][m] = bv.z; Bs[kk + 3][m] = bv.w;
        __syncthreads();
        #pragma unroll
        for (int k = 0; k < 16; k++) {
            const float4  a  = *(const float4*)&As[k][tm << 2];
            const double2 bd = *(const double2*)&Bs[k][tn << 2];
            const u64 b0 = __double_as_longlong(bd.x);
            const u64 b1 = __double_as_longlong(bd.y);
            const u64 a0 = pack2(a.x, a.x), a1 = pack2(a.y, a.y);
            const u64 a2 = pack2(a.z, a.z), a3 = pack2(a.w, a.w);
            fma2(acc[0][0], a0, b0); fma2(acc[0][1], a0, b1);
            fma2(acc[1][0], a1, b0); fma2(acc[1][1], a1, b1);
            fma2(acc[2][0], a2, b0); fma2(acc[2][1], a2, b1);
            fma2(acc[3][0], a3, b0); fma2(acc[3][1], a3, b1);
        }
        __syncthreads();
    }

    const float4 bias = *(const float4*)(bih + (gt << 6) + (tn << 2));
    const size_t gbase = (size_t)((pt << 6) + (tm << 2)) * DG + (gt << 6) + (tn << 2);
    #pragma unroll
    for (int i = 0; i < 4; i++) {
        float4 o;
        unpack2(acc[i][0], o.x, o.y);
        unpack2(acc[i][1], o.z, o.w);
        o.x += bias.x; o.y += bias.y; o.z += bias.z; o.w += bias.w;
        *(float4*)(g_gi + gbase + (size_t)i * DG) = o;
    }
}

// ---------------------------------------------------------------------------
// Kernel 3: persistent cluster recurrence, v3 (wavefront-optimal).
// 16 clusters x 8 CTAs x 512 threads. Warp = j-pair; lane = (b4, kc8):
// 4 batch cols per lane (register W reuse), kc splits k 8-way, shfl reduce.
// ---------------------------------------------------------------------------
#define CSZ 8
#define BPC 16
#define WROW 520                       // floats per (jp,gate) row (512 + pad)
#define HOFF0 (48 * WROW)              // 24960
#define HOFF1 (HOFF0 + 4096)
#define SMEM_F (HOFF1 + 4096)          // 33152 floats = 132608 B

// h (b, k) -> swizzled float offset: 16B unit u = b*64 + k/4,
// pu = u ^ (b&7) ^ 4*((k>>5)&1)
__device__ __forceinline__ int h_off(int b, int k) {
    const int u  = (b << 6) + (k >> 2);
    const int px = (b & 7) ^ (((k >> 5) & 1) << 2);
    return ((u ^ px) << 2) + (k & 3);
}

extern __shared__ float s_rec[];

__global__ void __cluster_dims__(CSZ, 1, 1) __launch_bounds__(512, 1)
k_rec(const float* __restrict__ Whh, const float* __restrict__ bhh,
      const float* __restrict__ hx, float* __restrict__ out, const size_t oe) {
    const int tid = threadIdx.x;
    uint32_t rank; asm("mov.u32 %0, %%cluster_ctarank;" : "=r"(rank));
    const int clu = blockIdx.x / CSZ;
    const int b0  = clu * BPC;

    uint32_t sbase;
    asm("{ .reg .u64 t; cvta.to.shared.u64 t, %1; cvt.u32.u64 %0, t; }"
        : "=r"(sbase) : "l"(s_rec));

    // --- resident W slice: row (jp*3+g); float off = pu*4 + (k&1)*2 + jl,
    //     pu = (k>>1) ^ (((k>>1)>>4)&7)  -> full-128B wavefronts in k-loop
    for (int idx = tid; idx < 96 * 64; idx += 512) {
        const int row = idx >> 6;
        const int g = row >> 5, jj = row & 31;
        const int jp = jj >> 1, jl = jj & 1;
        const int kq = (idx & 63) << 2;
        const float4 v = *(const float4*)(Whh +
            ((size_t)((g << 8) + ((int)rank << 5) + jj) << 8) + kq);
        float* rb = s_rec + (jp * 3 + g) * WROW;
        #pragma unroll
        for (int e = 0; e < 4; e++) {
            const int k  = kq + e;
            const int uw = k >> 1;
            const int pu = uw ^ ((uw >> 4) & 7);
            rb[(pu << 2) + ((k & 1) << 1) + jl] = (&v.x)[e];
        }
    }
    // --- initial h (swizzled; unit-granular so float4 store works)
    for (int idx = tid; idx < BPC * 64; idx += 512) {
        const int b = idx >> 6; const int k = (idx & 63) << 2;
        const float4 v = *(const float4*)(hx + ((size_t)(b0 + b) << 8) + k);
        *(float4*)&s_rec[HOFF0 + h_off(b, k)] = v;
    }

    int lmax = 0;
    #pragma unroll
    for (int i = 0; i < BPC; i++) lmax = max(lmax, g_len[b0 + i]);

    const int jp   = tid >> 5;               // warp = j-pair 0..15
    const int lane = tid & 31;
    const int b4   = lane & 3;
    const int kc   = lane >> 2;              // 0..7
    const int Jg   = ((int)rank << 5) + (jp << 1);

    const float* wr = s_rec + (jp * 3 + 0) * WROW;
    const float* wz = s_rec + (jp * 3 + 1) * WROW;
    const float* wn = s_rec + (jp * 3 + 2) * WROW;

    const float2 bh_r = *(const float2*)(bhh + Jg);
    const float2 bh_z = *(const float2*)(bhh + 256 + Jg);
    const float2 bh_n = *(const float2*)(bhh + 512 + Jg);

    int hb[4], sx[4], ho[4], blen[4], bglob[4];
    uint32_t rem0[4], rem1[4];
    #pragma unroll
    for (int q = 0; q < 4; q++) {
        const int b = b4 + (q << 2);
        hb[q] = b << 8;
        sx[q] = (b & 7) ^ ((kc & 1) << 2);
        ho[q] = h_off(b, Jg);
        bglob[q] = b0 + b;
        blen[q] = g_len[b0 + b];
        const uint32_t a0 = sbase + ((HOFF0 + ho[q]) << 2);
        const uint32_t a1 = sbase + ((HOFF1 + ho[q]) << 2);
        asm("mapa.shared::cluster.u32 %0, %1, %2;" : "=r"(rem0[q]) : "r"(a0), "r"(kc));
        asm("mapa.shared::cluster.u32 %0, %1, %2;" : "=r"(rem1[q]) : "r"(a1), "r"(kc));
    }
    const int ntrue = g_ntrue;

    asm volatile("barrier.cluster.arrive.aligned;" ::: "memory");
    asm volatile("barrier.cluster.wait.aligned;"   ::: "memory");

    for (int t = 0; t < lmax; t++) {
        const int cur = t & 1;
        const float* hc = s_rec + (cur ? HOFF1 : HOFF0);

        // prefetch gi + dest + hold (hidden under k-loop)
        float2 gi_r[4], gi_z[4], gi_n[4], hold[4];
        int dest[4];
        #pragma unroll
        for (int q = 0; q < 4; q++) {
            const int nflat = (t << 8) + bglob[q];
            const float* gp = g_gi + (size_t)nflat * DG;
            gi_r[q] = __ldg((const float2*)(gp + Jg));
            gi_z[q] = __ldg((const float2*)(gp + 256 + Jg));
            gi_n[q] = __ldg((const float2*)(gp + 512 + Jg));
            dest[q] = ((t < blen[q]) && (nflat < ntrue)) ? __ldg(&g_order[nflat]) : -1;
            hold[q] = *(const float2*)&hc[ho[q]];
        }

        u64 acc[3][4];
        #pragma unroll
        for (int g = 0; g < 3; g++)
            #pragma unroll
            for (int q = 0; q < 4; q++) acc[g][q] = 0ull;

        #pragma unroll 4
        for (int i = 0; i < 8; i++) {
            const int u0 = (kc << 4) + (i << 1);
            const int p0 = ((u0 ^ kc) << 2);
            const int p1 = (((u0 + 1) ^ kc) << 2);
            const double2 r01 = *(const double2*)(wr + p0);
            const double2 r23 = *(const double2*)(wr + p1);
            const double2 z01 = *(const double2*)(wz + p0);
            const double2 z23 = *(const double2*)(wz + p1);
            const double2 n01 = *(const double2*)(wn + p0);
            const double2 n23 = *(const double2*)(wn + p1);
            const int hu = (kc << 3) + i;
            #pragma unroll
            for (int q = 0; q < 4; q++) {
                const float4 hv = *(const float4*)(hc + hb[q] + ((hu ^ sx[q]) << 2));
                const u64 h0 = pack2(hv.x, hv.x), h1 = pack2(hv.y, hv.y);
                const u64 h2 = pack2(hv.z, hv.z), h3 = pack2(hv.w, hv.w);
                fma2(acc[0][q], h0, __double_as_longlong(r01.x));
                fma2(acc[0][q], h1, __double_as_longlong(r01.y));
                fma2(acc[0][q], h2, __double_as_longlong(r23.x));
                fma2(acc[0][q], h3, __double_as_longlong(r23.y));
                fma2(acc[1][q], h0, __double_as_longlong(z01.x));
                fma2(acc[1][q], h1, __double_as_longlong(z01.y));
                fma2(acc[1][q], h2, __double_as_longlong(z23.x));
                fma2(acc[1][q], h3, __double_as_longlong(z23.y));
                fma2(acc[2][q], h0, __double_as_longlong(n01.x));
                fma2(acc[2][q], h1, __double_as_longlong(n01.y));
                fma2(acc[2][q], h2, __double_as_longlong(n23.x));
                fma2(acc[2][q], h3, __double_as_longlong(n23.y));
            }
        }

        // reduce over kc (lane bits 2,3,4)
        #pragma unroll
        for (int g = 0; g < 3; g++)
            #pragma unroll
            for (int q = 0; q < 4; q++) {
                u64 v = acc[g][q];
                v = add2(v, __shfl_xor_sync(0xffffffffu, v, 4));
                v = add2(v, __shfl_xor_sync(0xffffffffu, v, 8));
                v = add2(v, __shfl_xor_sync(0xffffffffu, v, 16));
                acc[g][q] = v;
            }

        const int nxt = cur ^ 1;
        #pragma unroll
        for (int q = 0; q < 4; q++) {
            float ghr0, ghr1, ghz0, ghz1, ghn0, ghn1;
            unpack2(acc[0][q], ghr0, ghr1);
            unpack2(acc[1][q], ghz0, ghz1);
            unpack2(acc[2][q], ghn0, ghn1);
            float hn0, hn1;
            {
                const float r0 = 1.f / (1.f + __expf(-(gi_r[q].x + ghr0 + bh_r.x)));
                const float z0 = 1.f / (1.f + __expf(-(gi_z[q].x + ghz0 + bh_z.x)));
                const float n0 = tanh_ap(gi_n[q].x + r0 * (ghn0 + bh_n.x));
                hn0 = (1.f - z0) * n0 + z0 * hold[q].x;
                const float r1 = 1.f / (1.f + __expf(-(gi_r[q].y + ghr1 + bh_r.y)));
                const float z1 = 1.f / (1.f + __expf(-(gi_z[q].y + ghz1 + bh_z.y)));
                const float n1 = tanh_ap(gi_n[q].y + r1 * (ghn1 + bh_n.y));
                hn1 = (1.f - z1) * n1 + z1 * hold[q].y;
            }
            if (t >= blen[q]) { hn0 = hold[q].x; hn1 = hold[q].y; }

            const u64 pk = pack2(hn0, hn1);
            asm volatile("st.shared::cluster.b64 [%0], %1;"
                         :: "r"(nxt ? rem1[q] : rem0[q]), "l"(pk) : "memory");
            if (kc == 0 && dest[q] >= 0) {
                const size_t o = ((size_t)dest[q] << 8) + Jg;
                if (o + 1 < oe) *(float2*)(out + o) = make_float2(hn0, hn1);
            }
        }

        asm volatile("barrier.cluster.arrive.aligned;" ::: "memory");
        asm volatile("barrier.cluster.wait.aligned;"   ::: "memory");
    }

    // final hidden state
    if (kc == 0) {
        const float* hf = s_rec + ((lmax & 1) ? HOFF1 : HOFF0);
        #pragma unroll
        for (int q = 0; q < 4; q++) {
            const float2 hv = *(const float2*)&hf[ho[q]];
            const size_t o = ((size_t)DP << 8) + ((size_t)bglob[q] << 8) + Jg;
            if (o + 1 < oe) *(float2*)(out + o) = hv;
        }
    }
}

// ---------------------------------------------------------------------------
__global__ void k_zero(float* __restrict__ out, const size_t n) {
    size_t i = (size_t)blockIdx.x * blockDim.x + threadIdx.x;
    const size_t stride = (size_t)gridDim.x * blockDim.x;
    for (; i < n; i += stride) out[i] = 0.f;
}

// ---------------------------------------------------------------------------
extern "C" void kernel_launch(void* const* d_in, const int* in_sizes, int n_in,
                              void* d_out, int out_size) {
    const float* x    = (const float*)d_in[0];
    const float* hx   = (const float*)d_in[1];
    const int*   mask = (const int*)  d_in[2];
    const float* Wih  = (const float*)d_in[3];
    const float* Whh  = (const float*)d_in[4];
    const float* bih  = (const float*)d_in[5];
    const float* bhh  = (const float*)d_in[6];
    float* out = (float*)d_out;
    const size_t oe = (size_t)out_size;

    static int s_attr_done = 0;
    if (!s_attr_done) {
        cudaFuncSetAttribute(k_rec, cudaFuncAttributeMaxDynamicSharedMemorySize,
                             SMEM_F * 4);
        s_attr_done = 1;
    }

    k_prep<<<1, 1024>>>(mask);
    k_zero<<<2048, 256>>>(out, oe);
    k_gi<<<dim3(12, 2048), 256>>>(x, Wih, bih);
    k_rec<<<128, 512, SMEM_F * 4>>>(Whh, bhh, hx, out, oe);
}

// round 7
// speedup vs baseline: 1.8247x; 1.8247x over previous
#include <cuda_runtime.h>
#include <math.h>
#include <stdint.h>

#define DT 512
#define DB 256
#define DI 256
#define DH 256
#define DG 768
#define DP (DT * DB)

typedef unsigned long long u64;

// ---------------- device scratch ----------
__device__ int   g_src[DP];
__device__ int   g_order[DP];
__device__ int   g_len[DB];
__device__ int   g_maxlen;
__device__ int   g_ntrue;
__device__ float g_h0[DB * DH];
__device__ float g_h1[DB * DH];
__device__ float g_gi[(size_t)DP * DG];

// ---------------- f32x2 helpers ----------
__device__ __forceinline__ u64 pack2(float lo, float hi) {
    u64 r; asm("mov.b64 %0, {%1, %2};" : "=l"(r) : "f"(lo), "f"(hi)); return r;
}
__device__ __forceinline__ void unpack2(u64 v, float& lo, float& hi) {
    asm("mov.b64 {%0, %1}, %2;" : "=f"(lo), "=f"(hi) : "l"(v));
}
__device__ __forceinline__ void fma2(u64& d, u64 a, u64 b) {
    asm("fma.rn.f32x2 %0, %1, %2, %0;" : "+l"(d) : "l"(a), "l"(b));
}
__device__ __forceinline__ float tanh_ap(float x) {
    float r; asm("tanh.approx.f32 %0, %1;" : "=f"(r) : "f"(x)); return r;
}

// ---------------------------------------------------------------------------
// Kernel 1: lengths, packed mask, ranks, order[], src[]  (1 CTA, 1024 thr)
// ---------------------------------------------------------------------------
__global__ void k_prep(const int* __restrict__ mask) {
    __shared__ int sLen[DB];
    __shared__ int sWm[32], sWp[32];
    __shared__ int sMax;
    const int tid = threadIdx.x;
    if (tid < DB) sLen[tid] = 0;
    if (tid == 0) sMax = 0;
    __syncthreads();
    {
        const int b = tid & 255;
        int acc = 0;
        for (int t = tid >> 8; t < DT; t += 4) acc += (mask[(t << 8) + b] != 0) ? 1 : 0;
        atomicAdd(&sLen[b], acc);
    }
    __syncthreads();
    if (tid < DB) { g_len[tid] = sLen[tid]; atomicMax(&sMax, sLen[tid]); }
    __syncthreads();
    if (tid == 0) g_maxlen = sMax;

    const int base = tid << 7;
    int cm = 0, cp = 0;
    #pragma unroll 4
    for (int i = 0; i < 128; i++) {
        const int p = base + i;
        cm += (mask[p] != 0) ? 1 : 0;
        cp += ((p >> 8) < sLen[p & 255]) ? 1 : 0;
    }
    const int lane = tid & 31, wid = tid >> 5;
    int im = cm, ip = cp;
    #pragma unroll
    for (int d = 1; d < 32; d <<= 1) {
        const int um = __shfl_up_sync(0xffffffffu, im, d);
        const int up = __shfl_up_sync(0xffffffffu, ip, d);
        if (lane >= d) { im += um; ip += up; }
    }
    if (lane == 31) { sWm[wid] = im; sWp[wid] = ip; }
    __syncthreads();
    if (wid == 0) {
        const int am = sWm[lane], ap = sWp[lane];
        int jm = am, jp = ap;
        #pragma unroll
        for (int d = 1; d < 32; d <<= 1) {
            const int um = __shfl_up_sync(0xffffffffu, jm, d);
            const int up = __shfl_up_sync(0xffffffffu, jp, d);
            if (lane >= d) { jm += um; jp += up; }
        }
        sWm[lane] = jm - am;
        sWp[lane] = jp - ap;
        if (lane == 31) g_ntrue = jm;
    }
    __syncthreads();

    int mrank = sWm[wid] + im - cm;
    int prank = sWp[wid] + ip - cp;
    for (int i = 0; i < 128; i++) {
        const int p  = base + i;
        const int mt = (mask[p] != 0) ? 1 : 0;
        const int pt = ((p >> 8) < sLen[p & 255]) ? 1 : 0;
        if (mt) g_order[mrank] = p;
        g_src[p] = pt ? prank : -1;
        mrank += mt; prank += pt;
    }
    __syncthreads();
    for (int i = 0; i < 128; i++) {
        const int p = base + i;
        const int k = g_src[p];
        if (k >= 0) g_src[p] = g_order[k];
    }
}

// ---------------------------------------------------------------------------
// Kernel 2: gi = gather(x) @ W_ih^T + b_ih  (64x64x16 tile, f32x2)
// ---------------------------------------------------------------------------
__global__ void k_gi(const float* __restrict__ x,
                     const float* __restrict__ Wih,
                     const float* __restrict__ bih) {
    __shared__ float As[16][64];
    __shared__ float Bs[16][64];
    __shared__ int   sSrc[64];
    __shared__ int   sAny;
    const int tid = threadIdx.x;
    const int gt = blockIdx.x;
    const int pt = blockIdx.y;

    if (tid == 0) sAny = 0;
    __syncthreads();
    if (tid < 64) {
        const int s = g_src[(pt << 6) + tid];
        sSrc[tid] = (s >= 0) ? s : 0;
        if (s >= 0) sAny = 1;
    }
    __syncthreads();
    if (!sAny) return;

    u64 acc[4][2] = {{0ull, 0ull}, {0ull, 0ull}, {0ull, 0ull}, {0ull, 0ull}};
    const int tm = tid & 15, tn = tid >> 4;
    const int m  = tid >> 2;
    const int kk = (tid & 3) << 2;
    const float* xrow = x   + ((size_t)sSrc[m] << 8);
    const float* wrow = Wih + ((size_t)((gt << 6) + m) << 8);

    for (int k0 = 0; k0 < DI; k0 += 16) {
        const float4 av = *(const float4*)(xrow + k0 + kk);
        const float4 bv = *(const float4*)(wrow + k0 + kk);
        As[kk + 0][m] = av.x; As[kk + 1][m] = av.y; As[kk + 2][m] = av.z; As[kk + 3][m] = av.w;
        Bs[kk + 0][m] = bv.x; Bs[kk + 1][m] = bv.y; Bs[kk + 2][m] = bv.z; Bs[kk + 3][m] = bv.w;
        __syncthreads();
        #pragma unroll
        for (int k = 0; k < 16; k++) {
            const float4  a  = *(const float4*)&As[k][tm << 2];
            const double2 bd = *(const double2*)&Bs[k][tn << 2];
            const u64 b0 = __double_as_longlong(bd.x);
            const u64 b1 = __double_as_longlong(bd.y);
            const u64 a0 = pack2(a.x, a.x), a1 = pack2(a.y, a.y);
            const u64 a2 = pack2(a.z, a.z), a3 = pack2(a.w, a.w);
            fma2(acc[0][0], a0, b0); fma2(acc[0][1], a0, b1);
            fma2(acc[1][0], a1, b0); fma2(acc[1][1], a1, b1);
            fma2(acc[2][0], a2, b0); fma2(acc[2][1], a2, b1);
            fma2(acc[3][0], a3, b0); fma2(acc[3][1], a3, b1);
        }
        __syncthreads();
    }

    const float4 bias = *(const float4*)(bih + (gt << 6) + (tn << 2));
    const size_t gbase = (size_t)((pt << 6) + (tm << 2)) * DG + (gt << 6) + (tn << 2);
    #pragma unroll
    for (int i = 0; i < 4; i++) {
        float4 o;
        unpack2(acc[i][0], o.x, o.y);
        unpack2(acc[i][1], o.z, o.w);
        o.x += bias.x; o.y += bias.y; o.z += bias.z; o.w += bias.w;
        *(float4*)(g_gi + gbase + (size_t)i * DG) = o;
    }
}

// ---------------------------------------------------------------------------
// Kernel 3: one GRU step (launch-per-step, no cluster). Grid (16 jt, 8 bt),
// 256 threads. Thread = (jp 0..7, b-lane 0..31): 2j x 3 gates x 1b, full K.
// W j-pair interleaved in smem (broadcast LDS.128); h XOR-swizzled
// (4-wavefront LDS.128). No reductions, no inter-CTA traffic.
// ---------------------------------------------------------------------------
#define WSF (24 * 520)                     // W floats: 24 rows x (512+8)
#define STP_SMEMF (WSF + 32 * 256)         // + h tile 32b x 256k
#define STP_SMEMB (STP_SMEMF * 4)          // 82688 B

extern __shared__ float s_stp[];

__global__ void __launch_bounds__(256, 1)
k_step(const int t, const float* __restrict__ Whh, const float* __restrict__ bhh,
       float* __restrict__ out, const size_t oe) {
    if (t >= g_maxlen) return;
    const float* __restrict__ hin  = (t & 1) ? g_h1 : g_h0;
    float* __restrict__       hout = (t & 1) ? g_h0 : g_h1;

    const int tid = threadIdx.x;
    const int jp = tid >> 5, bl = tid & 31;
    const int jt = blockIdx.x, bt = blockIdx.y;
    const int bglob = (bt << 5) + bl;
    const int j0 = (jt << 4) + (jp << 1);

    // early scalar loads (latency hidden under smem fill + k-loop)
    const int nflat = (t << 8) + bglob;
    const int blen  = g_len[bglob];
    const int valid = (t < blen) ? 1 : 0;
    int dest = -1;
    if (valid && nflat < g_ntrue) dest = __ldg(&g_order[nflat]);
    const float* gp = g_gi + (size_t)nflat * DG;
    const float2 gi_r = __ldg((const float2*)(gp + j0));
    const float2 gi_z = __ldg((const float2*)(gp + 256 + j0));
    const float2 gi_n = __ldg((const float2*)(gp + 512 + j0));
    const float2 bh_r = __ldg((const float2*)(bhh + j0));
    const float2 bh_z = __ldg((const float2*)(bhh + 256 + j0));
    const float2 bh_n = __ldg((const float2*)(bhh + 512 + j0));
    const float2 hold = *(const float2*)(hin + ((size_t)bglob << 8) + j0);

    float* Ws = s_stp;
    float* Hs = s_stp + WSF;

    // W tile -> smem, j-pair interleaved: Ws[(jp*3+g)*520 + k*2 + jl]
    #pragma unroll
    for (int it = 0; it < 12; it++) {
        const int idx = tid + (it << 8);
        const int row = idx >> 6, f4 = idx & 63;
        const int g = row >> 4, jr = row & 15;
        const int jpl = jr >> 1, jl = jr & 1;
        const float4 v = *(const float4*)(Whh +
            ((size_t)((g << 8) + (jt << 4) + jr) << 8) + (f4 << 2));
        float* rb = Ws + (jpl * 3 + g) * 520 + jl;
        rb[(((f4 << 2) + 0) << 1)] = v.x;
        rb[(((f4 << 2) + 1) << 1)] = v.y;
        rb[(((f4 << 2) + 2) << 1)] = v.z;
        rb[(((f4 << 2) + 3) << 1)] = v.w;
    }
    // h tile -> smem, swizzled: unit u -> u ^ (b&7)
    #pragma unroll
    for (int it = 0; it < 8; it++) {
        const int idx = tid + (it << 8);
        const int b = idx >> 6, ub = idx & 63;
        const float4 v = *(const float4*)(hin + ((size_t)((bt << 5) + b) << 8) + (ub << 2));
        *(float4*)(Hs + (b << 8) + ((ub ^ (b & 7)) << 2)) = v;
    }
    __syncthreads();

    const float* wr = Ws + (jp * 3 + 0) * 520;
    const float* wz = Ws + (jp * 3 + 1) * 520;
    const float* wn = Ws + (jp * 3 + 2) * 520;
    const float* hrow = Hs + (bl << 8);
    const int hxor = bl & 7;

    u64 ar = 0ull, az = 0ull, an = 0ull;
    #pragma unroll 8
    for (int i = 0; i < 64; i++) {
        const float4 hv = *(const float4*)(hrow + ((i ^ hxor) << 2));
        const int o = i << 3;
        const double2 r01 = *(const double2*)(wr + o);
        const double2 r23 = *(const double2*)(wr + o + 4);
        const double2 z01 = *(const double2*)(wz + o);
        const double2 z23 = *(const double2*)(wz + o + 4);
        const double2 n01 = *(const double2*)(wn + o);
        const double2 n23 = *(const double2*)(wn + o + 4);
        const u64 h0 = pack2(hv.x, hv.x), h1 = pack2(hv.y, hv.y);
        const u64 h2 = pack2(hv.z, hv.z), h3 = pack2(hv.w, hv.w);
        fma2(ar, h0, __double_as_longlong(r01.x));
        fma2(ar, h1, __double_as_longlong(r01.y));
        fma2(ar, h2, __double_as_longlong(r23.x));
        fma2(ar, h3, __double_as_longlong(r23.y));
        fma2(az, h0, __double_as_longlong(z01.x));
        fma2(az, h1, __double_as_longlong(z01.y));
        fma2(az, h2, __double_as_longlong(z23.x));
        fma2(az, h3, __double_as_longlong(z23.y));
        fma2(an, h0, __double_as_longlong(n01.x));
        fma2(an, h1, __double_as_longlong(n01.y));
        fma2(an, h2, __double_as_longlong(n23.x));
        fma2(an, h3, __double_as_longlong(n23.y));
    }

    float ghr0, ghr1, ghz0, ghz1, ghn0, ghn1;
    unpack2(ar, ghr0, ghr1);
    unpack2(az, ghz0, ghz1);
    unpack2(an, ghn0, ghn1);

    float hn0, hn1;
    {
        const float r0 = 1.f / (1.f + __expf(-(gi_r.x + ghr0 + bh_r.x)));
        const float z0 = 1.f / (1.f + __expf(-(gi_z.x + ghz0 + bh_z.x)));
        const float n0 = tanh_ap(gi_n.x + r0 * (ghn0 + bh_n.x));
        hn0 = (1.f - z0) * n0 + z0 * hold.x;
        const float r1 = 1.f / (1.f + __expf(-(gi_r.y + ghr1 + bh_r.y)));
        const float z1 = 1.f / (1.f + __expf(-(gi_z.y + ghz1 + bh_z.y)));
        const float n1 = tanh_ap(gi_n.y + r1 * (ghn1 + bh_n.y));
        hn1 = (1.f - z1) * n1 + z1 * hold.y;
    }
    if (!valid) { hn0 = hold.x; hn1 = hold.y; }

    *(float2*)(hout + ((size_t)bglob << 8) + j0) = make_float2(hn0, hn1);
    if (dest >= 0) {
        const size_t o = ((size_t)dest << 8) + j0;
        if (o + 1 < oe) *(float2*)(out + o) = make_float2(hn0, hn1);
    }
}

// ---------------------------------------------------------------------------
// Small helpers
// ---------------------------------------------------------------------------
__global__ void k_zero4(float4* __restrict__ out, const size_t n4) {
    size_t i = (size_t)blockIdx.x * blockDim.x + threadIdx.x;
    const size_t stride = (size_t)gridDim.x * blockDim.x;
    const float4 z = make_float4(0.f, 0.f, 0.f, 0.f);
    for (; i < n4; i += stride) out[i] = z;
}

__global__ void k_init(const float* __restrict__ hx) {
    const int i = blockIdx.x * blockDim.x + threadIdx.x;
    if (i < DB * DH) g_h0[i] = hx[i];
}

__global__ void k_fin(float* __restrict__ out, const size_t oe) {
    const float* h = (g_maxlen & 1) ? g_h1 : g_h0;
    const int i = blockIdx.x * blockDim.x + threadIdx.x;
    if (i < DB * DH) {
        const size_t o = (size_t)DP * DH + i;
        if (o < oe) out[o] = h[i];
    }
}

// ---------------------------------------------------------------------------
extern "C" void kernel_launch(void* const* d_in, const int* in_sizes, int n_in,
                              void* d_out, int out_size) {
    const float* x    = (const float*)d_in[0];
    const float* hx   = (const float*)d_in[1];
    const int*   mask = (const int*)  d_in[2];
    const float* Wih  = (const float*)d_in[3];
    const float* Whh  = (const float*)d_in[4];
    const float* bih  = (const float*)d_in[5];
    const float* bhh  = (const float*)d_in[6];
    float* out = (float*)d_out;
    const size_t oe = (size_t)out_size;

    static int s_attr_done = 0;
    if (!s_attr_done) {
        cudaFuncSetAttribute(k_step, cudaFuncAttributeMaxDynamicSharedMemorySize,
                             STP_SMEMB);
        s_attr_done = 1;
    }

    k_prep<<<1, 1024>>>(mask);
    k_zero4<<<1024, 256>>>((float4*)out, oe >> 2);
    k_init<<<64, 1024>>>(hx);
    k_gi<<<dim3(12, 2048), 256>>>(x, Wih, bih);
    for (int t = 0; t < DT; ++t) {
        k_step<<<dim3(16, 8), 256, STP_SMEMB>>>(t, Whh, bhh, out, oe);
    }
    k_fin<<<64, 1024>>>(out, oe);
}

// round 8
// speedup vs baseline: 2.2749x; 1.2467x over previous
#include <cuda_runtime.h>
#include <math.h>
#include <stdint.h>

#define DT 512
#define DB 256
#define DI 256
#define DH 256
#define DG 768
#define DP (DT * DB)

typedef unsigned long long u64;

// ---------------- device scratch ----------
__device__ int      g_src[DP];
__device__ int      g_order[DP];
__device__ int      g_len[DB];
__device__ int      g_maxlen;
__device__ int      g_ntrue;
__device__ unsigned g_bar;
__device__ float    g_h0[DB * DH];
__device__ float    g_h1[DB * DH];
__device__ float    g_gi[(size_t)DP * DG];

// ---------------- f32x2 helpers ----------
__device__ __forceinline__ u64 pack2(float lo, float hi) {
    u64 r; asm("mov.b64 %0, {%1, %2};" : "=l"(r) : "f"(lo), "f"(hi)); return r;
}
__device__ __forceinline__ void unpack2(u64 v, float& lo, float& hi) {
    asm("mov.b64 {%0, %1}, %2;" : "=f"(lo), "=f"(hi) : "l"(v));
}
__device__ __forceinline__ void fma2(u64& d, u64 a, u64 b) {
    asm("fma.rn.f32x2 %0, %1, %2, %0;" : "+l"(d) : "l"(a), "l"(b));
}
__device__ __forceinline__ float tanh_ap(float x) {
    float r; asm("tanh.approx.f32 %0, %1;" : "=f"(r) : "f"(x)); return r;
}

// ---------------------------------------------------------------------------
// Kernel 1: lengths, packed mask, ranks, order[], src[]  (1 CTA, 1024 thr)
// ---------------------------------------------------------------------------
__global__ void k_prep(const int* __restrict__ mask) {
    __shared__ int sLen[DB];
    __shared__ int sWm[32], sWp[32];
    __shared__ int sMax;
    const int tid = threadIdx.x;
    if (tid == 0) g_bar = 0u;
    if (tid < DB) sLen[tid] = 0;
    if (tid == 0) sMax = 0;
    __syncthreads();
    {
        const int b = tid & 255;
        int acc = 0;
        for (int t = tid >> 8; t < DT; t += 4) acc += (mask[(t << 8) + b] != 0) ? 1 : 0;
        atomicAdd(&sLen[b], acc);
    }
    __syncthreads();
    if (tid < DB) { g_len[tid] = sLen[tid]; atomicMax(&sMax, sLen[tid]); }
    __syncthreads();
    if (tid == 0) g_maxlen = sMax;

    const int base = tid << 7;
    int cm = 0, cp = 0;
    #pragma unroll 4
    for (int i = 0; i < 128; i++) {
        const int p = base + i;
        cm += (mask[p] != 0) ? 1 : 0;
        cp += ((p >> 8) < sLen[p & 255]) ? 1 : 0;
    }
    const int lane = tid & 31, wid = tid >> 5;
    int im = cm, ip = cp;
    #pragma unroll
    for (int d = 1; d < 32; d <<= 1) {
        const int um = __shfl_up_sync(0xffffffffu, im, d);
        const int up = __shfl_up_sync(0xffffffffu, ip, d);
        if (lane >= d) { im += um; ip += up; }
    }
    if (lane == 31) { sWm[wid] = im; sWp[wid] = ip; }
    __syncthreads();
    if (wid == 0) {
        const int am = sWm[lane], ap = sWp[lane];
        int jm = am, jp = ap;
        #pragma unroll
        for (int d = 1; d < 32; d <<= 1) {
            const int um = __shfl_up_sync(0xffffffffu, jm, d);
            const int up = __shfl_up_sync(0xffffffffu, jp, d);
            if (lane >= d) { jm += um; jp += up; }
        }
        sWm[lane] = jm - am;
        sWp[lane] = jp - ap;
        if (lane == 31) g_ntrue = jm;
    }
    __syncthreads();

    int mrank = sWm[wid] + im - cm;
    int prank = sWp[wid] + ip - cp;
    for (int i = 0; i < 128; i++) {
        const int p  = base + i;
        const int mt = (mask[p] != 0) ? 1 : 0;
        const int pt = ((p >> 8) < sLen[p & 255]) ? 1 : 0;
        if (mt) g_order[mrank] = p;
        g_src[p] = pt ? prank : -1;
        mrank += mt; prank += pt;
    }
    __syncthreads();
    for (int i = 0; i < 128; i++) {
        const int p = base + i;
        const int k = g_src[p];
        if (k >= 0) g_src[p] = g_order[k];
    }
}

// ---------------------------------------------------------------------------
// Kernel 2: gi = gather(x) @ W_ih^T + b_ih  (64x64x16 tile, f32x2)
// ---------------------------------------------------------------------------
__global__ void k_gi(const float* __restrict__ x,
                     const float* __restrict__ Wih,
                     const float* __restrict__ bih) {
    __shared__ float As[16][64];
    __shared__ float Bs[16][64];
    __shared__ int   sSrc[64];
    __shared__ int   sAny;
    const int tid = threadIdx.x;
    const int gt = blockIdx.x;
    const int pt = blockIdx.y;

    if (tid == 0) sAny = 0;
    __syncthreads();
    if (tid < 64) {
        const int s = g_src[(pt << 6) + tid];
        sSrc[tid] = (s >= 0) ? s : 0;
        if (s >= 0) sAny = 1;
    }
    __syncthreads();
    if (!sAny) return;

    u64 acc[4][2] = {{0ull, 0ull}, {0ull, 0ull}, {0ull, 0ull}, {0ull, 0ull}};
    const int tm = tid & 15, tn = tid >> 4;
    const int m  = tid >> 2;
    const int kk = (tid & 3) << 2;
    const float* xrow = x   + ((size_t)sSrc[m] << 8);
    const float* wrow = Wih + ((size_t)((gt << 6) + m) << 8);

    for (int k0 = 0; k0 < DI; k0 += 16) {
        const float4 av = *(const float4*)(xrow + k0 + kk);
        const float4 bv = *(const float4*)(wrow + k0 + kk);
        As[kk + 0][m] = av.x; As[kk + 1][m] = av.y; As[kk + 2][m] = av.z; As[kk + 3][m] = av.w;
        Bs[kk + 0][m] = bv.x; Bs[kk + 1][m] = bv.y; Bs[kk + 2][m] = bv.z; Bs[kk + 3][m] = bv.w;
        __syncthreads();
        #pragma unroll
        for (int k = 0; k < 16; k++) {
            const float4  a  = *(const float4*)&As[k][tm << 2];
            const double2 bd = *(const double2*)&Bs[k][tn << 2];
            const u64 b0 = __double_as_longlong(bd.x);
            const u64 b1 = __double_as_longlong(bd.y);
            const u64 a0 = pack2(a.x, a.x), a1 = pack2(a.y, a.y);
            const u64 a2 = pack2(a.z, a.z), a3 = pack2(a.w, a.w);
            fma2(acc[0][0], a0, b0); fma2(acc[0][1], a0, b1);
            fma2(acc[1][0], a1, b0); fma2(acc[1][1], a1, b1);
            fma2(acc[2][0], a2, b0); fma2(acc[2][1], a2, b1);
            fma2(acc[3][0], a3, b0); fma2(acc[3][1], a3, b1);
        }
        __syncthreads();
    }

    const float4 bias = *(const float4*)(bih + (gt << 6) + (tn << 2));
    const size_t gbase = (size_t)((pt << 6) + (tm << 2)) * DG + (gt << 6) + (tn << 2);
    #pragma unroll
    for (int i = 0; i < 4; i++) {
        float4 o;
        unpack2(acc[i][0], o.x, o.y);
        unpack2(acc[i][1], o.z, o.w);
        o.x += bias.x; o.y += bias.y; o.z += bias.z; o.w += bias.w;
        *(float4*)(g_gi + gbase + (size_t)i * DG) = o;
    }
}

// ---------------------------------------------------------------------------
// Kernel 3: PERSISTENT recurrence. 128 CTAs (16 jt x 8 bt), 256 threads,
// single wave. W resident in smem for all steps; h ping-pongs through global
// (L2). Per-step sync = software global barrier (atomic counter + acquire
// spin) instead of kernel launch (~1us vs ~2.8us).
// ---------------------------------------------------------------------------
#define WSF (24 * 520)                     // W floats: 24 rows x (512+8)
#define STP_SMEMF (WSF + 32 * 256)         // + h tile 32b x 256k
#define STP_SMEMB (STP_SMEMF * 4)          // 82688 B
#define NCTA 128u

extern __shared__ float s_stp[];

__global__ void __launch_bounds__(256, 1)
k_recp(const float* __restrict__ Whh, const float* __restrict__ bhh,
       float* __restrict__ out, const size_t oe) {
    const int tid = threadIdx.x;
    const int jp = tid >> 5, bl = tid & 31;
    const int jt = blockIdx.x & 15, bt = blockIdx.x >> 4;
    const int bglob = (bt << 5) + bl;
    const int j0 = (jt << 4) + (jp << 1);

    float* Ws = s_stp;
    float* Hs = s_stp + WSF;

    // ---- W tile -> smem ONCE, j-pair interleaved: Ws[(jp*3+g)*520 + k*2 + jl]
    #pragma unroll
    for (int it = 0; it < 12; it++) {
        const int idx = tid + (it << 8);
        const int row = idx >> 6, f4 = idx & 63;
        const int g = row >> 4, jr = row & 15;
        const int jpl = jr >> 1, jl = jr & 1;
        const float4 v = *(const float4*)(Whh +
            ((size_t)((g << 8) + (jt << 4) + jr) << 8) + (f4 << 2));
        float* rb = Ws + (jpl * 3 + g) * 520 + jl;
        rb[(((f4 << 2) + 0) << 1)] = v.x;
        rb[(((f4 << 2) + 1) << 1)] = v.y;
        rb[(((f4 << 2) + 2) << 1)] = v.z;
        rb[(((f4 << 2) + 3) << 1)] = v.w;
    }

    // loop-invariant scalars
    const int lmax  = g_maxlen;
    const int ntrue = g_ntrue;
    const int blen  = g_len[bglob];
    const float2 bh_r = __ldg((const float2*)(bhh + j0));
    const float2 bh_z = __ldg((const float2*)(bhh + 256 + j0));
    const float2 bh_n = __ldg((const float2*)(bhh + 512 + j0));

    const float* wr = Ws + (jp * 3 + 0) * 520;
    const float* wz = Ws + (jp * 3 + 1) * 520;
    const float* wn = Ws + (jp * 3 + 2) * 520;
    const float* hrow = Hs + (bl << 8);
    const int hxor = bl & 7;

    for (int t = 0; t < lmax; t++) {
        const float* __restrict__ hin  = (t & 1) ? g_h1 : g_h0;
        float* __restrict__       hout = (t & 1) ? g_h0 : g_h1;

        // per-step scalar prefetch
        const int nflat = (t << 8) + bglob;
        const int valid = (t < blen) ? 1 : 0;
        int dest = -1;
        if (valid && nflat < ntrue) dest = __ldg(&g_order[nflat]);
        const float* gp = g_gi + (size_t)nflat * DG;
        const float2 gi_r = __ldg((const float2*)(gp + j0));
        const float2 gi_z = __ldg((const float2*)(gp + 256 + j0));
        const float2 gi_n = __ldg((const float2*)(gp + 512 + j0));
        const float2 hold = *(const float2*)(hin + ((size_t)bglob << 8) + j0);

        // h tile -> smem, swizzled: unit u -> u ^ (b&7)
        #pragma unroll
        for (int it = 0; it < 8; it++) {
            const int idx = tid + (it << 8);
            const int b = idx >> 6, ub = idx & 63;
            const float4 v = *(const float4*)(hin + ((size_t)((bt << 5) + b) << 8) + (ub << 2));
            *(float4*)(Hs + (b << 8) + ((ub ^ (b & 7)) << 2)) = v;
        }
        __syncthreads();

        u64 ar = 0ull, az = 0ull, an = 0ull;
        #pragma unroll 8
        for (int i = 0; i < 64; i++) {
            const float4 hv = *(const float4*)(hrow + ((i ^ hxor) << 2));
            const int o = i << 3;
            const double2 r01 = *(const double2*)(wr + o);
            const double2 r23 = *(const double2*)(wr + o + 4);
            const double2 z01 = *(const double2*)(wz + o);
            const double2 z23 = *(const double2*)(wz + o + 4);
            const double2 n01 = *(const double2*)(wn + o);
            const double2 n23 = *(const double2*)(wn + o + 4);
            const u64 h0 = pack2(hv.x, hv.x), h1 = pack2(hv.y, hv.y);
            const u64 h2 = pack2(hv.z, hv.z), h3 = pack2(hv.w, hv.w);
            fma2(ar, h0, __double_as_longlong(r01.x));
            fma2(ar, h1, __double_as_longlong(r01.y));
            fma2(ar, h2, __double_as_longlong(r23.x));
            fma2(ar, h3, __double_as_longlong(r23.y));
            fma2(az, h0, __double_as_longlong(z01.x));
            fma2(az, h1, __double_as_longlong(z01.y));
            fma2(az, h2, __double_as_longlong(z23.x));
            fma2(az, h3, __double_as_longlong(z23.y));
            fma2(an, h0, __double_as_longlong(n01.x));
            fma2(an, h1, __double_as_longlong(n01.y));
            fma2(an, h2, __double_as_longlong(n23.x));
            fma2(an, h3, __double_as_longlong(n23.y));
        }

        float ghr0, ghr1, ghz0, ghz1, ghn0, ghn1;
        unpack2(ar, ghr0, ghr1);
        unpack2(az, ghz0, ghz1);
        unpack2(an, ghn0, ghn1);

        float hn0, hn1;
        {
            const float r0 = 1.f / (1.f + __expf(-(gi_r.x + ghr0 + bh_r.x)));
            const float z0 = 1.f / (1.f + __expf(-(gi_z.x + ghz0 + bh_z.x)));
            const float n0 = tanh_ap(gi_n.x + r0 * (ghn0 + bh_n.x));
            hn0 = (1.f - z0) * n0 + z0 * hold.x;
            const float r1 = 1.f / (1.f + __expf(-(gi_r.y + ghr1 + bh_r.y)));
            const float z1 = 1.f / (1.f + __expf(-(gi_z.y + ghz1 + bh_z.y)));
            const float n1 = tanh_ap(gi_n.y + r1 * (ghn1 + bh_n.y));
            hn1 = (1.f - z1) * n1 + z1 * hold.y;
        }
        if (!valid) { hn0 = hold.x; hn1 = hold.y; }

        *(float2*)(hout + ((size_t)bglob << 8) + j0) = make_float2(hn0, hn1);
        if (dest >= 0) {
            const size_t o = ((size_t)dest << 8) + j0;
            if (o + 1 < oe) *(float2*)(out + o) = make_float2(hn0, hn1);
        }

        // ---- global barrier: fence + arrive + acquire-spin ----
        __threadfence();
        __syncthreads();          // all threads' stores issued + fenced
        if (tid == 0) {
            atomicAdd(&g_bar, 1u);
            const unsigned tgt = NCTA * (unsigned)(t + 1);
            unsigned v;
            do {
                asm volatile("ld.acquire.gpu.global.u32 %0, [%1];"
                             : "=r"(v) : "l"(&g_bar));
            } while (v < tgt);
        }
        __syncthreads();          // release whole CTA; also guards Hs reuse
    }
}

// ---------------------------------------------------------------------------
// Small helpers
// ---------------------------------------------------------------------------
__global__ void k_zero4(float4* __restrict__ out, const size_t n4) {
    size_t i = (size_t)blockIdx.x * blockDim.x + threadIdx.x;
    const size_t stride = (size_t)gridDim.x * blockDim.x;
    const float4 z = make_float4(0.f, 0.f, 0.f, 0.f);
    for (; i < n4; i += stride) out[i] = z;
}

__global__ void k_init(const float* __restrict__ hx) {
    const int i = blockIdx.x * blockDim.x + threadIdx.x;
    if (i < DB * DH) g_h0[i] = hx[i];
}

__global__ void k_fin(float* __restrict__ out, const size_t oe) {
    const float* h = (g_maxlen & 1) ? g_h1 : g_h0;
    const int i = blockIdx.x * blockDim.x + threadIdx.x;
    if (i < DB * DH) {
        const size_t o = (size_t)DP * DH + i;
        if (o < oe) out[o] = h[i];
    }
}

// ---------------------------------------------------------------------------
extern "C" void kernel_launch(void* const* d_in, const int* in_sizes, int n_in,
                              void* d_out, int out_size) {
    const float* x    = (const float*)d_in[0];
    const float* hx   = (const float*)d_in[1];
    const int*   mask = (const int*)  d_in[2];
    const float* Wih  = (const float*)d_in[3];
    const float* Whh  = (const float*)d_in[4];
    const float* bih  = (const float*)d_in[5];
    const float* bhh  = (const float*)d_in[6];
    float* out = (float*)d_out;
    const size_t oe = (size_t)out_size;

    static int s_attr_done = 0;
    if (!s_attr_done) {
        cudaFuncSetAttribute(k_recp, cudaFuncAttributeMaxDynamicSharedMemorySize,
                             STP_SMEMB);
        s_attr_done = 1;
    }

    k_prep<<<1, 1024>>>(mask);
    k_zero4<<<1024, 256>>>((float4*)out, oe >> 2);
    k_init<<<64, 1024>>>(hx);
    k_gi<<<dim3(12, 2048), 256>>>(x, Wih, bih);
    k_recp<<<128, 256, STP_SMEMB>>>(Whh, bhh, out, oe);
    k_fin<<<64, 1024>>>(out, oe);
}

// round 9
// speedup vs baseline: 2.6186x; 1.1511x over previous
#include <cuda_runtime.h>
#include <math.h>
#include <stdint.h>

#define DT 512
#define DB 256
#define DI 256
#define DH 256
#define DG 768
#define DP (DT * DB)

typedef unsigned long long u64;

// ---------------- device scratch ----------
__device__ int      g_src[DP];
__device__ int      g_order[DP];
__device__ int      g_len[DB];
__device__ int      g_maxlen;
__device__ int      g_ntrue;
__device__ unsigned g_barg[16 * 32];   // 16 group counters, 128B apart
__device__ float    g_h0[DB * DH];
__device__ float    g_h1[DB * DH];
__device__ float    g_gi[(size_t)DP * DG];

// ---------------- f32x2 helpers ----------
__device__ __forceinline__ u64 pack2(float lo, float hi) {
    u64 r; asm("mov.b64 %0, {%1, %2};" : "=l"(r) : "f"(lo), "f"(hi)); return r;
}
__device__ __forceinline__ void unpack2(u64 v, float& lo, float& hi) {
    asm("mov.b64 {%0, %1}, %2;" : "=f"(lo), "=f"(hi) : "l"(v));
}
__device__ __forceinline__ void fma2(u64& d, u64 a, u64 b) {
    asm("fma.rn.f32x2 %0, %1, %2, %0;" : "+l"(d) : "l"(a), "l"(b));
}
__device__ __forceinline__ float tanh_ap(float x) {
    float r; asm("tanh.approx.f32 %0, %1;" : "=f"(r) : "f"(x)); return r;
}

// ---------------------------------------------------------------------------
// Kernel 1: lengths, packed mask, ranks, order[], src[]  (1 CTA, 1024 thr)
// ---------------------------------------------------------------------------
__global__ void k_prep(const int* __restrict__ mask) {
    __shared__ int sLen[DB];
    __shared__ int sWm[32], sWp[32];
    __shared__ int sMax;
    const int tid = threadIdx.x;
    if (tid < 512) g_barg[tid] = 0u;
    if (tid < DB) sLen[tid] = 0;
    if (tid == 0) sMax = 0;
    __syncthreads();
    {
        const int b = tid & 255;
        int acc = 0;
        for (int t = tid >> 8; t < DT; t += 4) acc += (mask[(t << 8) + b] != 0) ? 1 : 0;
        atomicAdd(&sLen[b], acc);
    }
    __syncthreads();
    if (tid < DB) { g_len[tid] = sLen[tid]; atomicMax(&sMax, sLen[tid]); }
    __syncthreads();
    if (tid == 0) g_maxlen = sMax;

    const int base = tid << 7;
    int cm = 0, cp = 0;
    #pragma unroll 4
    for (int i = 0; i < 128; i++) {
        const int p = base + i;
        cm += (mask[p] != 0) ? 1 : 0;
        cp += ((p >> 8) < sLen[p & 255]) ? 1 : 0;
    }
    const int lane = tid & 31, wid = tid >> 5;
    int im = cm, ip = cp;
    #pragma unroll
    for (int d = 1; d < 32; d <<= 1) {
        const int um = __shfl_up_sync(0xffffffffu, im, d);
        const int up = __shfl_up_sync(0xffffffffu, ip, d);
        if (lane >= d) { im += um; ip += up; }
    }
    if (lane == 31) { sWm[wid] = im; sWp[wid] = ip; }
    __syncthreads();
    if (wid == 0) {
        const int am = sWm[lane], ap = sWp[lane];
        int jm = am, jp = ap;
        #pragma unroll
        for (int d = 1; d < 32; d <<= 1) {
            const int um = __shfl_up_sync(0xffffffffu, jm, d);
            const int up = __shfl_up_sync(0xffffffffu, jp, d);
            if (lane >= d) { jm += um; jp += up; }
        }
        sWm[lane] = jm - am;
        sWp[lane] = jp - ap;
        if (lane == 31) g_ntrue = jm;
    }
    __syncthreads();

    int mrank = sWm[wid] + im - cm;
    int prank = sWp[wid] + ip - cp;
    for (int i = 0; i < 128; i++) {
        const int p  = base + i;
        const int mt = (mask[p] != 0) ? 1 : 0;
        const int pt = ((p >> 8) < sLen[p & 255]) ? 1 : 0;
        if (mt) g_order[mrank] = p;
        g_src[p] = pt ? prank : -1;
        mrank += mt; prank += pt;
    }
    __syncthreads();
    for (int i = 0; i < 128; i++) {
        const int p = base + i;
        const int k = g_src[p];
        if (k >= 0) g_src[p] = g_order[k];
    }
}

// ---------------------------------------------------------------------------
// Kernel 2: gi = gather(x) @ W_ih^T + b_ih.
// 128x128 tile, 256 threads, 8x8 register tile (f32x2), XOR-16 k-half swizzle
// on smem columns (conflict-free fills AND reads). FMA-issue bound.
// ---------------------------------------------------------------------------
#define GROW 132

__global__ void __launch_bounds__(256)
k_gi(const float* __restrict__ x,
     const float* __restrict__ Wih,
     const float* __restrict__ bih) {
    __shared__ float As[16 * GROW];
    __shared__ float Bs[16 * GROW];
    __shared__ int   sSrc[128];
    __shared__ int   sAny;
    const int tid = threadIdx.x;
    const int gt = blockIdx.x;     // 0..5  (768/128)
    const int pt = blockIdx.y;     // 0..1023

    if (tid == 0) sAny = 0;
    __syncthreads();
    if (tid < 128) {
        const int s = g_src[(pt << 7) + tid];
        sSrc[tid] = (s >= 0) ? s : 0;
        if (s >= 0) sAny = 1;
    }
    __syncthreads();
    if (!sAny) return;

    const int tx = tid & 15, ty = tid >> 4;
    const int m0 = ty << 3;            // 8 m rows
    const int n0 = tx << 2;            // n cols {n0..n0+3} and {64+n0..}

    // fill mapping: thread -> (row fm, k-half fk), swizzled column fm^(fk?16:0)
    const int fm = tid >> 1;
    const int fk = (tid & 1) << 3;
    const int fc = fm ^ (fk << 1);     // column with XOR-16 swizzle for fk=8
    const float* xrow = x   + ((size_t)sSrc[fm] << 8);
    const float* wrow = Wih + ((size_t)((gt << 7) + fm) << 8);

    u64 acc[8][4];
    #pragma unroll
    for (int m = 0; m < 8; m++)
        #pragma unroll
        for (int n = 0; n < 4; n++) acc[m][n] = 0ull;

    for (int k0 = 0; k0 < DI; k0 += 16) {
        const float4 av0 = *(const float4*)(xrow + k0 + fk);
        const float4 av1 = *(const float4*)(xrow + k0 + fk + 4);
        const float4 bv0 = *(const float4*)(wrow + k0 + fk);
        const float4 bv1 = *(const float4*)(wrow + k0 + fk + 4);
        __syncthreads();
        As[(fk + 0) * GROW + fc] = av0.x; As[(fk + 1) * GROW + fc] = av0.y;
        As[(fk + 2) * GROW + fc] = av0.z; As[(fk + 3) * GROW + fc] = av0.w;
        As[(fk + 4) * GROW + fc] = av1.x; As[(fk + 5) * GROW + fc] = av1.y;
        As[(fk + 6) * GROW + fc] = av1.z; As[(fk + 7) * GROW + fc] = av1.w;
        Bs[(fk + 0) * GROW + fc] = bv0.x; Bs[(fk + 1) * GROW + fc] = bv0.y;
        Bs[(fk + 2) * GROW + fc] = bv0.z; Bs[(fk + 3) * GROW + fc] = bv0.w;
        Bs[(fk + 4) * GROW + fc] = bv1.x; Bs[(fk + 5) * GROW + fc] = bv1.y;
        Bs[(fk + 6) * GROW + fc] = bv1.z; Bs[(fk + 7) * GROW + fc] = bv1.w;
        __syncthreads();

        #pragma unroll
        for (int k = 0; k < 16; k++) {
            const int xr = (k & 8) << 1;              // 0 or 16 (column XOR)
            const float* ar = As + k * GROW + (m0 ^ xr);
            const float* br = Bs + k * GROW;
            const int cn = n0 ^ xr;
            const float4  a0  = *(const float4*)(ar);
            const float4  a1  = *(const float4*)(ar + 4);
            const double2 bL  = *(const double2*)(br + cn);
            const double2 bH  = *(const double2*)(br + 64 + cn);
            const u64 bl0 = __double_as_longlong(bL.x);
            const u64 bl1 = __double_as_longlong(bL.y);
            const u64 bh0 = __double_as_longlong(bH.x);
            const u64 bh1 = __double_as_longlong(bH.y);
            const float am[8] = {a0.x, a0.y, a0.z, a0.w, a1.x, a1.y, a1.z, a1.w};
            #pragma unroll
            for (int m = 0; m < 8; m++) {
                const u64 p = pack2(am[m], am[m]);
                fma2(acc[m][0], p, bl0);
                fma2(acc[m][1], p, bl1);
                fma2(acc[m][2], p, bh0);
                fma2(acc[m][3], p, bh1);
            }
        }
    }

    const float4 biasA = *(const float4*)(bih + (gt << 7) + n0);
    const float4 biasB = *(const float4*)(bih + (gt << 7) + 64 + n0);
    #pragma unroll
    for (int m = 0; m < 8; m++) {
        const int row = (pt << 7) + m0 + m;
        float4 vA, vB;
        unpack2(acc[m][0], vA.x, vA.y);
        unpack2(acc[m][1], vA.z, vA.w);
        unpack2(acc[m][2], vB.x, vB.y);
        unpack2(acc[m][3], vB.z, vB.w);
        vA.x += biasA.x; vA.y += biasA.y; vA.z += biasA.z; vA.w += biasA.w;
        vB.x += biasB.x; vB.y += biasB.y; vB.z += biasB.z; vB.w += biasB.w;
        float* orow = g_gi + (size_t)row * DG + (gt << 7);
        *(float4*)(orow + n0)      = vA;
        *(float4*)(orow + 64 + n0) = vB;
    }
}

// ---------------------------------------------------------------------------
// Kernel 3: PERSISTENT recurrence. 128 CTAs (16 jt x 8 bt), 256 threads,
// single wave. W resident in smem; h ping-pongs through global (L2).
// Per-step sync = PER-GROUP (bt) software barrier: bar.sync + thread0
// red.release + ld.acquire spin + bar.sync. Groups fully independent.
// ---------------------------------------------------------------------------
#define WSF (24 * 520)                     // W floats: 24 rows x (512+8)
#define STP_SMEMF (WSF + 32 * 256)         // + h tile 32b x 256k
#define STP_SMEMB (STP_SMEMF * 4)          // 82688 B

extern __shared__ float s_stp[];

__global__ void __launch_bounds__(256, 1)
k_recp(const float* __restrict__ Whh, const float* __restrict__ bhh,
       float* __restrict__ out, const size_t oe) {
    const int tid = threadIdx.x;
    const int jp = tid >> 5, bl = tid & 31;
    const int jt = blockIdx.x & 15, bt = blockIdx.x >> 4;
    const int bglob = (bt << 5) + bl;
    const int j0 = (jt << 4) + (jp << 1);
    unsigned* bar = &g_barg[bt << 5];

    float* Ws = s_stp;
    float* Hs = s_stp + WSF;

    // ---- W tile -> smem ONCE, j-pair interleaved: Ws[(jp*3+g)*520 + k*2 + jl]
    #pragma unroll
    for (int it = 0; it < 12; it++) {
        const int idx = tid + (it << 8);
        const int row = idx >> 6, f4 = idx & 63;
        const int g = row >> 4, jr = row & 15;
        const int jpl = jr >> 1, jl = jr & 1;
        const float4 v = *(const float4*)(Whh +
            ((size_t)((g << 8) + (jt << 4) + jr) << 8) + (f4 << 2));
        float* rb = Ws + (jpl * 3 + g) * 520 + jl;
        rb[(((f4 << 2) + 0) << 1)] = v.x;
        rb[(((f4 << 2) + 1) << 1)] = v.y;
        rb[(((f4 << 2) + 2) << 1)] = v.z;
        rb[(((f4 << 2) + 3) << 1)] = v.w;
    }

    // loop-invariant scalars; group lmax over this bt's 32 columns
    int lmax = 0;
    #pragma unroll 8
    for (int i = 0; i < 32; i++) lmax = max(lmax, g_len[(bt << 5) + i]);
    const int ntrue = g_ntrue;
    const int blen  = g_len[bglob];
    const float2 bh_r = __ldg((const float2*)(bhh + j0));
    const float2 bh_z = __ldg((const float2*)(bhh + 256 + j0));
    const float2 bh_n = __ldg((const float2*)(bhh + 512 + j0));

    const float* wr = Ws + (jp * 3 + 0) * 520;
    const float* wz = Ws + (jp * 3 + 1) * 520;
    const float* wn = Ws + (jp * 3 + 2) * 520;
    const float* hrow = Hs + (bl << 8);
    const int hxor = bl & 7;

    for (int t = 0; t < lmax; t++) {
        const float* __restrict__ hin  = (t & 1) ? g_h1 : g_h0;
        float* __restrict__       hout = (t & 1) ? g_h0 : g_h1;

        // per-step scalar prefetch
        const int nflat = (t << 8) + bglob;
        const int valid = (t < blen) ? 1 : 0;
        int dest = -1;
        if (valid && nflat < ntrue) dest = __ldg(&g_order[nflat]);
        const float* gp = g_gi + (size_t)nflat * DG;
        const float2 gi_r = __ldg((const float2*)(gp + j0));
        const float2 gi_z = __ldg((const float2*)(gp + 256 + j0));
        const float2 gi_n = __ldg((const float2*)(gp + 512 + j0));
        const float2 hold = *(const float2*)(hin + ((size_t)bglob << 8) + j0);

        // h tile -> smem, swizzled: unit u -> u ^ (b&7)
        #pragma unroll
        for (int it = 0; it < 8; it++) {
            const int idx = tid + (it << 8);
            const int b = idx >> 6, ub = idx & 63;
            const float4 v = *(const float4*)(hin + ((size_t)((bt << 5) + b) << 8) + (ub << 2));
            *(float4*)(Hs + (b << 8) + ((ub ^ (b & 7)) << 2)) = v;
        }
        __syncthreads();

        u64 ar = 0ull, az = 0ull, an = 0ull;
        #pragma unroll 8
        for (int i = 0; i < 64; i++) {
            const float4 hv = *(const float4*)(hrow + ((i ^ hxor) << 2));
            const int o = i << 3;
            const double2 r01 = *(const double2*)(wr + o);
            const double2 r23 = *(const double2*)(wr + o + 4);
            const double2 z01 = *(const double2*)(wz + o);
            const double2 z23 = *(const double2*)(wz + o + 4);
            const double2 n01 = *(const double2*)(wn + o);
            const double2 n23 = *(const double2*)(wn + o + 4);
            const u64 h0 = pack2(hv.x, hv.x), h1 = pack2(hv.y, hv.y);
            const u64 h2 = pack2(hv.z, hv.z), h3 = pack2(hv.w, hv.w);
            fma2(ar, h0, __double_as_longlong(r01.x));
            fma2(ar, h1, __double_as_longlong(r01.y));
            fma2(ar, h2, __double_as_longlong(r23.x));
            fma2(ar, h3, __double_as_longlong(r23.y));
            fma2(az, h0, __double_as_longlong(z01.x));
            fma2(az, h1, __double_as_longlong(z01.y));
            fma2(az, h2, __double_as_longlong(z23.x));
            fma2(az, h3, __double_as_longlong(z23.y));
            fma2(an, h0, __double_as_longlong(n01.x));
            fma2(an, h1, __double_as_longlong(n01.y));
            fma2(an, h2, __double_as_longlong(n23.x));
            fma2(an, h3, __double_as_longlong(n23.y));
        }

        float ghr0, ghr1, ghz0, ghz1, ghn0, ghn1;
        unpack2(ar, ghr0, ghr1);
        unpack2(az, ghz0, ghz1);
        unpack2(an, ghn0, ghn1);

        float hn0, hn1;
        {
            const float r0 = 1.f / (1.f + __expf(-(gi_r.x + ghr0 + bh_r.x)));
            const float z0 = 1.f / (1.f + __expf(-(gi_z.x + ghz0 + bh_z.x)));
            const float n0 = tanh_ap(gi_n.x + r0 * (ghn0 + bh_n.x));
            hn0 = (1.f - z0) * n0 + z0 * hold.x;
            const float r1 = 1.f / (1.f + __expf(-(gi_r.y + ghr1 + bh_r.y)));
            const float z1 = 1.f / (1.f + __expf(-(gi_z.y + ghz1 + bh_z.y)));
            const float n1 = tanh_ap(gi_n.y + r1 * (ghn1 + bh_n.y));
            hn1 = (1.f - z1) * n1 + z1 * hold.y;
        }
        if (!valid) { hn0 = hold.x; hn1 = hold.y; }

        *(float2*)(hout + ((size_t)bglob << 8) + j0) = make_float2(hn0, hn1);
        if (dest >= 0) {
            const size_t o = ((size_t)dest << 8) + j0;
            if (o + 1 < oe) *(float2*)(out + o) = make_float2(hn0, hn1);
        }

        // ---- group barrier: bar + thread0 release-arrive + acquire-spin + bar
        __syncthreads();
        if (tid == 0) {
            asm volatile("red.release.gpu.global.add.u32 [%0], 1;"
                         :: "l"(bar) : "memory");
            const unsigned tgt = 16u * (unsigned)(t + 1);
            unsigned v;
            do {
                asm volatile("ld.acquire.gpu.global.u32 %0, [%1];"
                             : "=r"(v) : "l"(bar));
            } while (v < tgt);
        }
        __syncthreads();
    }

    // final hidden state for this bt-slice (written by jt==0 CTA of the group)
    if (jt == 0) {
        const float* hf = (lmax & 1) ? g_h1 : g_h0;
        const size_t obase = (size_t)DP << 8;
        for (int idx = tid; idx < 32 * 64; idx += 256) {
            const int b  = (bt << 5) + (idx >> 6);
            const int kq = (idx & 63) << 2;
            const size_t o = obase + ((size_t)b << 8) + kq;
            const float4 v = *(const float4*)(hf + ((size_t)b << 8) + kq);
            if (o + 3 < oe) *(float4*)(out + o) = v;
        }
    }
}

// ---------------------------------------------------------------------------
// Small helpers
// ---------------------------------------------------------------------------
__global__ void k_zero4(float4* __restrict__ out, const size_t n4) {
    size_t i = (size_t)blockIdx.x * blockDim.x + threadIdx.x;
    const size_t stride = (size_t)gridDim.x * blockDim.x;
    const float4 z = make_float4(0.f, 0.f, 0.f, 0.f);
    for (; i < n4; i += stride) out[i] = z;
}

__global__ void k_init(const float* __restrict__ hx) {
    const int i = blockIdx.x * blockDim.x + threadIdx.x;
    if (i < DB * DH) g_h0[i] = hx[i];
}

// ---------------------------------------------------------------------------
extern "C" void kernel_launch(void* const* d_in, const int* in_sizes, int n_in,
                              void* d_out, int out_size) {
    const float* x    = (const float*)d_in[0];
    const float* hx   = (const float*)d_in[1];
    const int*   mask = (const int*)  d_in[2];
    const float* Wih  = (const float*)d_in[3];
    const float* Whh  = (const float*)d_in[4];
    const float* bih  = (const float*)d_in[5];
    const float* bhh  = (const float*)d_in[6];
    float* out = (float*)d_out;
    const size_t oe = (size_t)out_size;

    static int s_attr_done = 0;
    if (!s_attr_done) {
        cudaFuncSetAttribute(k_recp, cudaFuncAttributeMaxDynamicSharedMemorySize,
                             STP_SMEMB);
        s_attr_done = 1;
    }

    k_prep<<<1, 1024>>>(mask);
    k_zero4<<<1024, 256>>>((float4*)out, oe >> 2);
    k_init<<<64, 1024>>>(hx);
    k_gi<<<dim3(6, 1024), 256>>>(x, Wih, bih);
    k_recp<<<128, 256, STP_SMEMB>>>(Whh, bhh, out, oe);
}